// round 9
// baseline (speedup 1.0000x reference)
#include <cuda_runtime.h>
#include <math.h>

#define Bn 8
#define Nn 8192
#define Sn 2048
#define Dn 64
#define KS 32
#define MTOT (Bn*Sn*KS)            /* 524288 rows through the MLP */
#define R2c 0.25f

#define OXY2 (Bn*3*Sn)             /* 49152  */
#define ONP  (2*Bn*3*Sn)           /* 98304  */
#define OFPS (ONP + Bn*128*Sn)     /* 2195456 */

/* ------------------------- static device scratch ------------------------- */
__device__ float  g_pts_t[(size_t)Bn*Nn*Dn];   /* [B][N][64] */
__device__ float  g_newxyz[Bn*Sn*3];
__device__ int    g_fps[Bn*Sn];
__device__ int    g_idx[Bn*Sn*KS];
__device__ float  g_base[(size_t)Bn*Sn*64];
__device__ float  g_h0[(size_t)MTOT*64];
__device__ float  g_h1[(size_t)MTOT*64];
__device__ float  g_mx[(size_t)Bn*Sn*128];
__device__ float  g_mn[(size_t)Bn*Sn*128];
__device__ double g_sum[3][128];
__device__ double g_sq[3][128];
__device__ float  g_sc[3][128];
__device__ float  g_sh[3][128];
/* morton-sorted copies for FPS */
__device__ float  g_sx[Bn][Nn], g_sy[Bn][Nn], g_sz[Bn][Nn];
__device__ int    g_perm[Bn][Nn];

/* ------------------------- packed f32x2 helpers -------------------------- */
typedef unsigned long long ull;
__device__ __forceinline__ ull pk2(float lo, float hi) {
    ull r; asm("mov.b64 %0,{%1,%2};" : "=l"(r) : "f"(lo), "f"(hi)); return r;
}
__device__ __forceinline__ void upk2(ull v, float& lo, float& hi) {
    asm("mov.b64 {%0,%1},%2;" : "=f"(lo), "=f"(hi) : "l"(v));
}
__device__ __forceinline__ ull add2(ull a, ull b) {
    ull r; asm("add.rn.f32x2 %0,%1,%2;" : "=l"(r) : "l"(a), "l"(b)); return r;
}
__device__ __forceinline__ ull mul2(ull a, ull b) {
    ull r; asm("mul.rn.f32x2 %0,%1,%2;" : "=l"(r) : "l"(a), "l"(b)); return r;
}

/* ------------------------------- zero stats ------------------------------ */
__global__ void k_zero() {
    int t = threadIdx.x;
    if (t < 128) for (int l = 0; l < 3; l++) { g_sum[l][t] = 0.0; g_sq[l][t] = 0.0; }
}

/* --------------------------- points transpose ---------------------------- */
__global__ void k_transpose(const float* __restrict__ pts) {
    __shared__ float tile[32][33];
    int b = blockIdx.z, n0 = blockIdx.x * 32, c0 = blockIdx.y * 32;
    int tx = threadIdx.x, ty = threadIdx.y;
    for (int i = ty; i < 32; i += 8)
        tile[i][tx] = pts[((size_t)b*Dn + c0 + i)*Nn + n0 + tx];
    __syncthreads();
    for (int i = ty; i < 32; i += 8)
        g_pts_t[((size_t)b*Nn + n0 + i)*Dn + c0 + tx] = tile[tx][i];
}

/* ------------------------ morton counting sort --------------------------- */
__device__ __forceinline__ int spread3(int v) {
    return (v & 1) | ((v & 2) << 2) | ((v & 4) << 4);
}
__global__ void __launch_bounds__(1024) k_sort(const float* __restrict__ xyz) {
    __shared__ int hist[512];
    int b = blockIdx.x, t = threadIdx.x;
    const float* xb = xyz + (size_t)b*3*Nn;
    for (int i = t; i < 512; i += 1024) hist[i] = 0;
    __syncthreads();
    int cells[8];
#pragma unroll
    for (int j = 0; j < 8; j++) {
        int i = t*8 + j;
        float x = xb[i], y = xb[Nn+i], z = xb[2*Nn+i];
        int qx = min(7, max(0, (int)floorf(x + 4.0f)));
        int qy = min(7, max(0, (int)floorf(y + 4.0f)));
        int qz = min(7, max(0, (int)floorf(z + 4.0f)));
        cells[j] = (spread3(qx) << 2) | (spread3(qy) << 1) | spread3(qz);
        atomicAdd(&hist[cells[j]], 1);
    }
    __syncthreads();
    if (t == 0) {
        int acc = 0;
        for (int c = 0; c < 512; c++) { int h = hist[c]; hist[c] = acc; acc += h; }
    }
    __syncthreads();
#pragma unroll
    for (int j = 0; j < 8; j++) {
        int i = t*8 + j;
        int pos = atomicAdd(&hist[cells[j]], 1);
        g_sx[b][pos] = xb[i]; g_sy[b][pos] = xb[Nn+i]; g_sz[b][pos] = xb[2*Nn+i];
        g_perm[b][pos] = i;
    }
}

/* ---------------------------------- FPS ---------------------------------- */
/* one block per batch; morton-sorted xyz in smem; packed f32x2 exact math.
   Warp bounding-sphere pruning (conservative, exact). ALL tie-breaks use the
   ORIGINAL point index to bit-match jnp.argmax on the unsorted array. */
__global__ void __launch_bounds__(1024) k_fps(const float* __restrict__ xyz) {
    extern __shared__ float sm[];
    float* sx = sm; float* sy = sm + Nn; float* sz = sm + 2*Nn;
    int* sperm = (int*)(sm + 3*Nn);
    __shared__ unsigned s_dv[2][32];   /* warp max dist bits   */
    __shared__ int      s_do[2][32];   /* winner original idx  */
    __shared__ int      s_ds[2][32];   /* winner sorted idx    */
    __shared__ float s_cx[32], s_cy[32], s_cz[32], s_r[32];
    int b = blockIdx.x, t = threadIdx.x, warp = t >> 5, lane = t & 31;
    for (int i = t; i < Nn; i += 1024) {
        sx[i] = g_sx[b][i]; sy[i] = g_sy[b][i]; sz[i] = g_sz[b][i];
        sperm[i] = g_perm[b][i];
    }
    if (t < 32) { s_dv[0][t] = __float_as_uint(1e10f); s_do[0][t] = 0; s_ds[0][t] = 0; }
    __syncthreads();
    ull px2[4], py2[4], pz2[4];
    float dist[8];
#pragma unroll
    for (int j = 0; j < 4; j++) {
        int i = t*8 + 2*j;
        px2[j] = pk2(sx[i], sx[i+1]);
        py2[j] = pk2(sy[i], sy[i+1]);
        pz2[j] = pk2(sz[i], sz[i+1]);
        dist[2*j] = 1e10f; dist[2*j+1] = 1e10f;
    }
    /* per-warp bounding sphere over its 256 contiguous (morton-local) pts */
    {
        float sxx = 0.f, syy = 0.f, szz = 0.f;
#pragma unroll
        for (int j = 0; j < 8; j++) {
            int i = t*8 + j;
            sxx += sx[i]; syy += sy[i]; szz += sz[i];
        }
#pragma unroll
        for (int o = 16; o > 0; o >>= 1) {
            sxx += __shfl_xor_sync(0xffffffffu, sxx, o);
            syy += __shfl_xor_sync(0xffffffffu, syy, o);
            szz += __shfl_xor_sync(0xffffffffu, szz, o);
        }
        float cx = sxx*(1.f/256.f), cy = syy*(1.f/256.f), cz = szz*(1.f/256.f);
        float r2 = 0.f;
#pragma unroll
        for (int j = 0; j < 8; j++) {
            int i = t*8 + j;
            float dx = sx[i]-cx, dy = sy[i]-cy, dz = sz[i]-cz;
            r2 = fmaxf(r2, dx*dx + dy*dy + dz*dz);
        }
        unsigned r2m = __reduce_max_sync(0xffffffffu, __float_as_uint(r2));
        if (lane == 0) {
            s_cx[warp] = cx; s_cy[warp] = cy; s_cz[warp] = cz;
            s_r[warp] = sqrtf(__uint_as_float(r2m))*1.001f + 1e-6f;
        }
    }
    /* first sample = original point 0 */
    const float* xb = xyz + (size_t)b*3*Nn;
    float fx = xb[0], fy = xb[Nn], fz = xb[2*Nn];
    if (t == 0) g_fps[b*Sn] = 0;
    __syncthreads();
    for (int it = 1; it < Sn; it++) {
        int p = it & 1;
        /* conservative skip test (warp-uniform) */
        float ccx = s_cx[warp], ccy = s_cy[warp], ccz = s_cz[warp], rr = s_r[warp];
        float dcx = fx-ccx, dcy = fy-ccy, dcz = fz-ccz;
        float dc2 = dcx*dcx + dcy*dcy + dcz*dcz;
        float lb  = sqrtf(dc2)*0.9995f - rr;
        float wprev = __uint_as_float(s_dv[p^1][warp]);
        bool skip = (lb > 0.f) && (lb*lb*0.998f > wprev);
        if (skip) {
            if (lane == 0) {
                s_dv[p][warp] = s_dv[p^1][warp];
                s_do[p][warp] = s_do[p^1][warp];
                s_ds[p][warp] = s_ds[p^1][warp];
            }
        } else {
            ull nx = pk2(-fx, -fx), ny = pk2(-fy, -fy), nz = pk2(-fz, -fz);
            float bv = -1.0f;
#pragma unroll
            for (int j = 0; j < 4; j++) {
                ull dx = add2(px2[j], nx);
                ull dy = add2(py2[j], ny);
                ull dz = add2(pz2[j], nz);
                ull s  = add2(add2(mul2(dx,dx), mul2(dy,dy)), mul2(dz,dz));
                float dlo, dhi; upk2(s, dlo, dhi);
                float n0 = fminf(dist[2*j],   dlo); dist[2*j]   = n0;
                float n1 = fminf(dist[2*j+1], dhi); dist[2*j+1] = n1;
                bv = fmaxf(bv, fmaxf(n0, n1));
            }
            /* warp max value (positive float bits are u32-monotonic) */
            unsigned dvb  = __float_as_uint(bv);
            unsigned wmax = __reduce_max_sync(0xffffffffu, dvb);
            /* per-thread best ORIGINAL index among dist[j]==wmax */
            float wmf = __uint_as_float(wmax);
            int morig = 0x7fffffff, msort = 0;
#pragma unroll
            for (int j = 0; j < 8; j++) {
                if (dist[j] == wmf) {
                    int o = sperm[t*8 + j];
                    if (o < morig) { morig = o; msort = t*8 + j; }
                }
            }
            int worig = __reduce_min_sync(0xffffffffu, morig);
            unsigned msk = __ballot_sync(0xffffffffu, morig == worig);
            int src = __ffs(msk) - 1;
            int wsort = __shfl_sync(0xffffffffu, msort, src);
            if (lane == 0) {
                s_dv[p][warp] = wmax;
                s_do[p][warp] = worig;
                s_ds[p][warp] = wsort;
            }
        }
        __syncthreads();
        /* stage 2: every warp reduces the 32 per-warp results redundantly */
        unsigned v    = s_dv[p][lane];
        unsigned gmax = __reduce_max_sync(0xffffffffu, v);
        int od        = (v == gmax) ? s_do[p][lane] : 0x7fffffff;
        int gorig     = __reduce_min_sync(0xffffffffu, od);
        unsigned m2   = __ballot_sync(0xffffffffu, od == gorig);
        int src2      = __ffs(m2) - 1;
        int gsort     = __shfl_sync(0xffffffffu, s_ds[p][lane], src2);
        fx = sx[gsort]; fy = sy[gsort]; fz = sz[gsort];
        if (t == 0) g_fps[b*Sn + it] = gorig;
    }
}

/* -------------------- new_xyz gather + small outputs --------------------- */
__global__ void k_newxyz(const float* __restrict__ xyz, float* __restrict__ out) {
    int i = blockIdx.x * blockDim.x + threadIdx.x;     /* center id 0..16383 */
    if (i >= Bn*Sn) return;
    int b = i / Sn, s = i % Sn;
    int n = g_fps[i];
    const float* xb = xyz + (size_t)b*3*Nn;
    float x = xb[n], y = xb[Nn+n], z = xb[2*Nn+n];
    g_newxyz[i*3+0]=x; g_newxyz[i*3+1]=y; g_newxyz[i*3+2]=z;
    out[((size_t)b*3+0)*Sn + s] = x;
    out[((size_t)b*3+1)*Sn + s] = y;
    out[((size_t)b*3+2)*Sn + s] = z;
    out[OXY2 + ((size_t)b*3+0)*Sn + s] = x;
    out[OXY2 + ((size_t)b*3+1)*Sn + s] = y;
    out[OXY2 + ((size_t)b*3+2)*Sn + s] = z;
    out[OFPS + i] = (float)n;
}

/* ------------------------------ ball query ------------------------------- */
#define BQC 2048
__global__ void __launch_bounds__(256) k_ballquery(const float* __restrict__ xyz) {
    __shared__ float sx[BQC], sy[BQC], sz[BQC];
    int blk = blockIdx.x;               /* 64 blocks: 8 per batch */
    int b = blk >> 3;
    int center = b*Sn + (blk & 7)*256 + threadIdx.x;
    int t = threadIdx.x;
    float cx = g_newxyz[center*3+0], cy = g_newxyz[center*3+1], cz = g_newxyz[center*3+2];
    const float* xb = xyz + (size_t)b*3*Nn;
    int found = 0, first = -1;
    for (int ch = 0; ch < Nn; ch += BQC) {
        for (int i = t; i < BQC; i += 256) {
            sx[i] = xb[ch+i]; sy[i] = xb[Nn+ch+i]; sz[i] = xb[2*Nn+ch+i];
        }
        __syncthreads();
        if (!__all_sync(0xffffffffu, found >= KS)) {
            for (int i = 0; i < BQC && found < KS; i++) {
                float dx = __fadd_rn(cx, -sx[i]);
                float dy = __fadd_rn(cy, -sy[i]);
                float dz = __fadd_rn(cz, -sz[i]);
                float d2 = __fadd_rn(__fadd_rn(__fmul_rn(dx,dx), __fmul_rn(dy,dy)),
                                     __fmul_rn(dz,dz));
                if (d2 <= R2c) {
                    if (first < 0) first = ch + i;
                    g_idx[center*KS + found] = ch + i;
                    found++;
                }
            }
        }
        if (__syncthreads_and(found >= KS)) break;
    }
    for (int i = found; i < KS; i++) g_idx[center*KS + i] = first;
}

/* -------------------- center-feature GEMV (layer-0 base) ----------------- */
__global__ void __launch_bounds__(256) k_base(const float* __restrict__ W0) {
    __shared__ float ws[67*64];
    __shared__ float cf[64*64];
    __shared__ float cxyz[64*3];
    int t = threadIdx.x;
    int c0 = blockIdx.x * 64;
    int b = c0 / Sn;
    for (int i = t; i < 67*64; i += 256) {
        int cc = i >> 6, o = i & 63;
        ws[i] = (cc < 3) ? W0[(size_t)o*131 + cc] : W0[(size_t)o*131 + 67 + (cc - 3)];
    }
    for (int i = t; i < 64*16; i += 256) {
        int row = i >> 4, seg = i & 15;
        int n = g_fps[c0 + row];
        float4 v = *(const float4*)&g_pts_t[((size_t)b*Nn + n)*Dn + seg*4];
        *(float4*)&cf[row*64 + seg*4] = v;
    }
    for (int i = t; i < 192; i += 256) cxyz[i] = g_newxyz[c0*3 + i];
    __syncthreads();
    int o4 = (t & 15) * 4, cg = t >> 4;
    float acc[4][4];
#pragma unroll
    for (int k = 0; k < 4; k++)
#pragma unroll
        for (int j = 0; j < 4; j++) acc[k][j] = 0.f;
#pragma unroll
    for (int cc = 0; cc < 3; cc++) {
        float4 wv = *(const float4*)&ws[cc*64 + o4];
#pragma unroll
        for (int k = 0; k < 4; k++) {
            float h = -cxyz[(cg*4 + k)*3 + cc];
            acc[k][0] += h*wv.x; acc[k][1] += h*wv.y;
            acc[k][2] += h*wv.z; acc[k][3] += h*wv.w;
        }
    }
#pragma unroll 8
    for (int cc = 3; cc < 67; cc++) {
        float4 wv = *(const float4*)&ws[cc*64 + o4];
#pragma unroll
        for (int k = 0; k < 4; k++) {
            float h = cf[(cg*4 + k)*64 + (cc - 3)];
            acc[k][0] += h*wv.x; acc[k][1] += h*wv.y;
            acc[k][2] += h*wv.z; acc[k][3] += h*wv.w;
        }
    }
#pragma unroll
    for (int k = 0; k < 4; k++) {
        float4 v = make_float4(acc[k][0], acc[k][1], acc[k][2], acc[k][3]);
        *(float4*)&g_base[(size_t)(c0 + cg*4 + k)*64 + o4] = v;
    }
}

#define FMA4(A, H, WV) { (A)[0] += (H)*(WV).x; (A)[1] += (H)*(WV).y; \
                         (A)[2] += (H)*(WV).z; (A)[3] += (H)*(WV).w; }

/* ------------------------------ layer 0 ---------------------------------- */
/* block: 4 tiles x (2 centers = 64 rows) x 64 outs; weights loaded once */
__global__ void __launch_bounds__(128) k_layer0(const float* __restrict__ xyz,
                                                const float* __restrict__ W0) {
    __shared__ float hs[64*72];
    __shared__ float ws[72*64];
    __shared__ int   idx_s[64];
    __shared__ float bs[128];
    __shared__ float ssum[64], ssq[64];
    int t = threadIdx.x;
    int b = (blockIdx.x * 8) / Sn;
    if (t < 64) { ssum[t] = 0.f; ssq[t] = 0.f; }
    for (int i = t; i < 72*64; i += 128) {
        int cc = i >> 6, o = i & 63;
        float v = 0.f;
        if (cc < 64)      v = W0[(size_t)o*131 + 3 + cc];
        else if (cc < 67) v = W0[(size_t)o*131 + (cc - 64)];
        ws[cc*64 + o] = v;
    }
    const float* xb = xyz + (size_t)b*3*Nn;
    int rg = t >> 4, og = t & 15;
    float tps[4] = {0,0,0,0}, tpq[4] = {0,0,0,0};
    for (int tile = 0; tile < 4; tile++) {
        int c0 = blockIdx.x * 8 + tile * 2;
        __syncthreads();
        if (t < 64) idx_s[t] = g_idx[c0*KS + t];
        bs[t] = g_base[(size_t)c0*64 + t];
        __syncthreads();
        for (int i = t; i < 64*16; i += 128) {
            int row = i >> 4, seg = i & 15;
            int n = idx_s[row];
            float4 v = *(const float4*)&g_pts_t[((size_t)b*Nn + n)*Dn + seg*4];
            *(float4*)&hs[row*72 + seg*4] = v;
        }
        for (int i = t; i < 64*8; i += 128) {
            int row = i >> 3, cc = i & 7;
            int n = idx_s[row];
            float v = 0.f;
            if (cc < 3) v = xb[cc*Nn + n];
            hs[row*72 + 64 + cc] = v;
        }
        __syncthreads();
        float acc[32];
#pragma unroll
        for (int i = 0; i < 32; i++) acc[i] = 0.f;
#pragma unroll
        for (int cs = 0; cs < 72; cs += 4) {
            float4 wv[4];
#pragma unroll
            for (int i = 0; i < 4; i++) wv[i] = *(const float4*)&ws[(cs+i)*64 + og*4];
#pragma unroll
            for (int j = 0; j < 8; j++) {
                float4 hv = *(const float4*)&hs[(rg*8+j)*72 + cs];
                FMA4(&acc[j*4], hv.x, wv[0]);
                FMA4(&acc[j*4], hv.y, wv[1]);
                FMA4(&acc[j*4], hv.z, wv[2]);
                FMA4(&acc[j*4], hv.w, wv[3]);
            }
        }
#pragma unroll
        for (int j = 0; j < 8; j++) {
            int row = rg*8 + j;
            int cl = row >> 5;
            float4 zv;
            zv.x = acc[j*4+0] + bs[cl*64 + og*4+0];
            zv.y = acc[j*4+1] + bs[cl*64 + og*4+1];
            zv.z = acc[j*4+2] + bs[cl*64 + og*4+2];
            zv.w = acc[j*4+3] + bs[cl*64 + og*4+3];
            *(float4*)&g_h0[((size_t)c0*KS + row)*64 + og*4] = zv;
            tps[0]+=zv.x; tps[1]+=zv.y; tps[2]+=zv.z; tps[3]+=zv.w;
            tpq[0]+=zv.x*zv.x; tpq[1]+=zv.y*zv.y; tpq[2]+=zv.z*zv.z; tpq[3]+=zv.w*zv.w;
        }
    }
#pragma unroll
    for (int i = 0; i < 4; i++) {
        atomicAdd(&ssum[og*4+i], tps[i]);
        atomicAdd(&ssq[og*4+i],  tpq[i]);
    }
    __syncthreads();
    if (t < 64) {
        atomicAdd(&g_sum[0][t], (double)ssum[t]);
        atomicAdd(&g_sq[0][t],  (double)ssq[t]);
    }
}

/* ------------------------------ layer 1 ---------------------------------- */
/* block: 4 tiles of 64 rows; weights loaded once */
__global__ void __launch_bounds__(128) k_layer1(const float* __restrict__ W1) {
    __shared__ float hs[64*64];
    __shared__ float ws[64*64];
    __shared__ float ssum[64], ssq[64];
    int t = threadIdx.x;
    if (t < 64) { ssum[t] = 0.f; ssq[t] = 0.f; }
    for (int i = t; i < 64*64; i += 128) {
        int cc = i >> 6, o = i & 63;
        ws[cc*64 + o] = W1[(size_t)o*64 + cc];
    }
    int rg = t >> 4, og = t & 15;
    float tps[4] = {0,0,0,0}, tpq[4] = {0,0,0,0};
    for (int tile = 0; tile < 4; tile++) {
        size_t m0 = (size_t)blockIdx.x * 256 + tile * 64;
        __syncthreads();
        for (int i = t; i < 64*16; i += 128) {
            int row = i >> 4, seg = i & 15;
            float4 v = *(const float4*)&g_h0[(m0 + row)*64 + seg*4];
            v.x = fmaxf(g_sc[0][seg*4+0]*v.x + g_sh[0][seg*4+0], 0.f);
            v.y = fmaxf(g_sc[0][seg*4+1]*v.y + g_sh[0][seg*4+1], 0.f);
            v.z = fmaxf(g_sc[0][seg*4+2]*v.z + g_sh[0][seg*4+2], 0.f);
            v.w = fmaxf(g_sc[0][seg*4+3]*v.w + g_sh[0][seg*4+3], 0.f);
            *(float4*)&hs[row*64 + seg*4] = v;
        }
        __syncthreads();
        float acc[32];
#pragma unroll
        for (int i = 0; i < 32; i++) acc[i] = 0.f;
#pragma unroll
        for (int cs = 0; cs < 64; cs += 4) {
            float4 wv[4];
#pragma unroll
            for (int i = 0; i < 4; i++) wv[i] = *(const float4*)&ws[(cs+i)*64 + og*4];
#pragma unroll
            for (int j = 0; j < 8; j++) {
                float4 hv = *(const float4*)&hs[(rg*8+j)*64 + cs];
                FMA4(&acc[j*4], hv.x, wv[0]);
                FMA4(&acc[j*4], hv.y, wv[1]);
                FMA4(&acc[j*4], hv.z, wv[2]);
                FMA4(&acc[j*4], hv.w, wv[3]);
            }
        }
#pragma unroll
        for (int j = 0; j < 8; j++) {
            int row = rg*8 + j;
            float4 zv = make_float4(acc[j*4+0], acc[j*4+1], acc[j*4+2], acc[j*4+3]);
            *(float4*)&g_h1[(m0 + row)*64 + og*4] = zv;
            tps[0]+=zv.x; tps[1]+=zv.y; tps[2]+=zv.z; tps[3]+=zv.w;
            tpq[0]+=zv.x*zv.x; tpq[1]+=zv.y*zv.y; tpq[2]+=zv.z*zv.z; tpq[3]+=zv.w*zv.w;
        }
    }
#pragma unroll
    for (int i = 0; i < 4; i++) {
        atomicAdd(&ssum[og*4+i], tps[i]);
        atomicAdd(&ssq[og*4+i],  tpq[i]);
    }
    __syncthreads();
    if (t < 64) {
        atomicAdd(&g_sum[1][t], (double)ssum[t]);
        atomicAdd(&g_sq[1][t],  (double)ssq[t]);
    }
}

/* ------------------------------ layer 2 ---------------------------------- */
/* block: 2 tiles of (2 centers x 128 outs); weights once; separate scratch */
__global__ void __launch_bounds__(256) k_layer2(const float* __restrict__ W2) {
    extern __shared__ float dyn[];
    float* hs    = dyn;                  /* 4096  */
    float* ws    = dyn + 4096;           /* 8192  */
    float* redmx = dyn + 4096 + 8192;    /* 1024  */
    float* redmn = redmx + 1024;         /* 1024  */
    float* ssum  = redmn + 1024;         /* 128   */
    float* ssq   = ssum + 128;           /* 128   */
    int t = threadIdx.x;
    if (t < 128) { ssum[t] = 0.f; ssq[t] = 0.f; }
    for (int i = t; i < 64*128; i += 256) {
        int cc = i >> 7, o = i & 127;
        ws[cc*128 + o] = W2[(size_t)o*64 + cc];
    }
    int rg = t >> 5, og = t & 31;
    float tps[4] = {0,0,0,0}, tpq[4] = {0,0,0,0};
    for (int tile = 0; tile < 2; tile++) {
        int c0 = blockIdx.x * 4 + tile * 2;
        size_t m0 = (size_t)c0 * KS;
        __syncthreads();
        for (int i = t; i < 64*16; i += 256) {
            int row = i >> 4, seg = i & 15;
            float4 v = *(const float4*)&g_h1[(m0 + row)*64 + seg*4];
            v.x = fmaxf(g_sc[1][seg*4+0]*v.x + g_sh[1][seg*4+0], 0.f);
            v.y = fmaxf(g_sc[1][seg*4+1]*v.y + g_sh[1][seg*4+1], 0.f);
            v.z = fmaxf(g_sc[1][seg*4+2]*v.z + g_sh[1][seg*4+2], 0.f);
            v.w = fmaxf(g_sc[1][seg*4+3]*v.w + g_sh[1][seg*4+3], 0.f);
            *(float4*)&hs[row*64 + seg*4] = v;
        }
        __syncthreads();
        float acc[32];
#pragma unroll
        for (int i = 0; i < 32; i++) acc[i] = 0.f;
#pragma unroll
        for (int cs = 0; cs < 64; cs += 4) {
            float4 wv[4];
#pragma unroll
            for (int i = 0; i < 4; i++) wv[i] = *(const float4*)&ws[(cs+i)*128 + og*4];
#pragma unroll
            for (int j = 0; j < 8; j++) {
                float4 hv = *(const float4*)&hs[(rg*8+j)*64 + cs];
                FMA4(&acc[j*4], hv.x, wv[0]);
                FMA4(&acc[j*4], hv.y, wv[1]);
                FMA4(&acc[j*4], hv.z, wv[2]);
                FMA4(&acc[j*4], hv.w, wv[3]);
            }
        }
#pragma unroll
        for (int i = 0; i < 4; i++) {
            int o = og*4 + i;
            float mx = -1e30f, mn = 1e30f, ps = 0.f, pq = 0.f;
#pragma unroll
            for (int j = 0; j < 8; j++) {
                float z = acc[j*4+i];
                mx = fmaxf(mx, z); mn = fminf(mn, z);
                ps += z; pq += z*z;
            }
            redmx[rg*128 + o] = mx;
            redmn[rg*128 + o] = mn;
            tps[i] += ps; tpq[i] += pq;
        }
        __syncthreads();
        {
            int cl = t >> 7, o = t & 127;
            float mx = -1e30f, mn = 1e30f;
#pragma unroll
            for (int r = 0; r < 4; r++) {
                mx = fmaxf(mx, redmx[(cl*4+r)*128 + o]);
                mn = fminf(mn, redmn[(cl*4+r)*128 + o]);
            }
            g_mx[(size_t)(c0+cl)*128 + o] = mx;
            g_mn[(size_t)(c0+cl)*128 + o] = mn;
        }
    }
#pragma unroll
    for (int i = 0; i < 4; i++) {
        atomicAdd(&ssum[og*4+i], tps[i]);
        atomicAdd(&ssq[og*4+i],  tpq[i]);
    }
    __syncthreads();
    if (t < 128) {
        atomicAdd(&g_sum[2][t], (double)ssum[t]);
        atomicAdd(&g_sq[2][t],  (double)ssq[t]);
    }
}

/* ----------------------------- BN fold ----------------------------------- */
__global__ void k_stats(int layer, const float* __restrict__ gm,
                        const float* __restrict__ bt, int nch) {
    int c = threadIdx.x;
    if (c < nch) {
        double mu = g_sum[layer][c] / (double)MTOT;
        double vr = g_sq[layer][c] / (double)MTOT - mu*mu;
        float sc = gm[c] * rsqrtf((float)vr + 1e-5f);
        g_sc[layer][c] = sc;
        g_sh[layer][c] = bt[c] - (float)mu * sc;
    }
}

/* ----------------------------- final pool -------------------------------- */
__global__ void k_final(float* __restrict__ out) {
    int i = blockIdx.x * blockDim.x + threadIdx.x;
    if (i >= Bn*Sn*128) return;
    int center = i >> 7, o = i & 127;
    int b = center / Sn, s = center % Sn;
    float sc = g_sc[2][o], sh = g_sh[2][o];
    float z = (sc >= 0.f) ? g_mx[(size_t)center*128 + o] : g_mn[(size_t)center*128 + o];
    out[ONP + ((size_t)b*128 + o)*Sn + s] = fmaxf(sc*z + sh, 0.f);
}

/* ------------------------------- launch ---------------------------------- */
extern "C" void kernel_launch(void* const* d_in, const int* in_sizes, int n_in,
                              void* d_out, int out_size) {
    const float* xyz = (const float*)d_in[0];
    const float* pts = (const float*)d_in[1];
    const float* W0  = (const float*)d_in[2];
    const float* g0  = (const float*)d_in[3];
    const float* b0  = (const float*)d_in[4];
    const float* W1  = (const float*)d_in[5];
    const float* g1  = (const float*)d_in[6];
    const float* b1  = (const float*)d_in[7];
    const float* W2  = (const float*)d_in[8];
    const float* g2  = (const float*)d_in[9];
    const float* b2  = (const float*)d_in[10];
    float* out = (float*)d_out;

    static bool attr_done = false;
    if (!attr_done) {
        cudaFuncSetAttribute(k_fps, cudaFuncAttributeMaxDynamicSharedMemorySize,
                             4*Nn*sizeof(float));
        cudaFuncSetAttribute(k_layer2, cudaFuncAttributeMaxDynamicSharedMemorySize,
                             (4096+8192+1024+1024+256)*sizeof(float));
        attr_done = true;
    }

    k_zero<<<1, 128>>>();
    k_transpose<<<dim3(Nn/32, Dn/32, Bn), dim3(32, 8)>>>(pts);
    k_sort<<<Bn, 1024>>>(xyz);                        /* ncu alignment: fps = #6 */
    k_fps<<<Bn, 1024, 4*Nn*sizeof(float)>>>(xyz);
    k_newxyz<<<(Bn*Sn + 255)/256, 256>>>(xyz, out);
    k_ballquery<<<64, 256>>>(xyz);
    k_base<<<256, 256>>>(W0);
    k_layer0<<<Bn*Sn/8, 128>>>(xyz, W0);
    k_stats<<<1, 128>>>(0, g0, b0, 64);
    k_layer1<<<MTOT/256, 128>>>(W1);
    k_stats<<<1, 128>>>(1, g1, b1, 64);
    k_layer2<<<Bn*Sn/4, 256, (4096+8192+1024+1024+256)*sizeof(float)>>>(W2);
    k_stats<<<1, 128>>>(2, g2, b2, 128);
    k_final<<<(Bn*Sn*128 + 255)/256, 256>>>(out);
}

// round 10
// speedup vs baseline: 1.3395x; 1.3395x over previous
#include <cuda_runtime.h>
#include <math.h>

#define Bn 8
#define Nn 8192
#define Sn 2048
#define Dn 64
#define KS 32
#define MTOT (Bn*Sn*KS)            /* 524288 rows through the MLP */
#define R2c 0.25f

#define OXY2 (Bn*3*Sn)             /* 49152  */
#define ONP  (2*Bn*3*Sn)           /* 98304  */
#define OFPS (ONP + Bn*128*Sn)     /* 2195456 */

/* ------------------------- static device scratch ------------------------- */
__device__ float  g_pts_t[(size_t)Bn*Nn*Dn];   /* [B][N][64] */
__device__ float  g_newxyz[Bn*Sn*3];
__device__ int    g_fps[Bn*Sn];
__device__ int    g_idx[Bn*Sn*KS];
__device__ float  g_base[(size_t)Bn*Sn*64];
__device__ float  g_h0[(size_t)MTOT*64];
__device__ float  g_h1[(size_t)MTOT*64];
__device__ float  g_mx[(size_t)Bn*Sn*128];
__device__ float  g_mn[(size_t)Bn*Sn*128];
__device__ double g_sum[3][128];
__device__ double g_sq[3][128];
__device__ float  g_sc[3][128];
__device__ float  g_sh[3][128];

/* ------------------------- packed f32x2 helpers -------------------------- */
typedef unsigned long long ull;
__device__ __forceinline__ ull pk2(float lo, float hi) {
    ull r; asm("mov.b64 %0,{%1,%2};" : "=l"(r) : "f"(lo), "f"(hi)); return r;
}
__device__ __forceinline__ void upk2(ull v, float& lo, float& hi) {
    asm("mov.b64 {%0,%1},%2;" : "=f"(lo), "=f"(hi) : "l"(v));
}
__device__ __forceinline__ ull add2(ull a, ull b) {
    ull r; asm("add.rn.f32x2 %0,%1,%2;" : "=l"(r) : "l"(a), "l"(b)); return r;
}
__device__ __forceinline__ ull mul2(ull a, ull b) {
    ull r; asm("mul.rn.f32x2 %0,%1,%2;" : "=l"(r) : "l"(a), "l"(b)); return r;
}

/* ------------------------------- zero stats ------------------------------ */
__global__ void k_zero() {
    int t = threadIdx.x;
    if (t < 128) for (int l = 0; l < 3; l++) { g_sum[l][t] = 0.0; g_sq[l][t] = 0.0; }
}

/* dummy: positions k_fps as the 4th app launch so ncu (-s 5 -c 1) profiles it */
__global__ void k_dummy() {}

/* --------------------------- points transpose ---------------------------- */
__global__ void k_transpose(const float* __restrict__ pts) {
    __shared__ float tile[32][33];
    int b = blockIdx.z, n0 = blockIdx.x * 32, c0 = blockIdx.y * 32;
    int tx = threadIdx.x, ty = threadIdx.y;
    for (int i = ty; i < 32; i += 8)
        tile[i][tx] = pts[((size_t)b*Dn + c0 + i)*Nn + n0 + tx];
    __syncthreads();
    for (int i = ty; i < 32; i += 8)
        g_pts_t[((size_t)b*Nn + n0 + i)*Dn + c0 + tx] = tile[tx][i];
}

/* ---------------------------------- FPS ---------------------------------- */
/* R4 version: one block per batch; xyz in smem; packed f32x2 exact math;
   REDUX argmax with lowest-index tie-break; ONE barrier per iteration. */
__global__ void __launch_bounds__(1024) k_fps(const float* __restrict__ xyz) {
    extern __shared__ float sm[];
    float* sx = sm; float* sy = sm + Nn; float* sz = sm + 2*Nn;
    __shared__ unsigned s_dv[2][32];
    __shared__ unsigned s_di[2][32];
    int b = blockIdx.x, t = threadIdx.x;
    int warp = t >> 5, lane = t & 31;
    const float* xb = xyz + (size_t)b*3*Nn;
    for (int i = t; i < Nn; i += 1024) { sx[i]=xb[i]; sy[i]=xb[Nn+i]; sz[i]=xb[2*Nn+i]; }
    __syncthreads();
    ull px2[4], py2[4], pz2[4];
    float dist[8];
#pragma unroll
    for (int j = 0; j < 4; j++) {
        int i = t*8 + 2*j;
        px2[j] = pk2(sx[i], sx[i+1]);
        py2[j] = pk2(sy[i], sy[i+1]);
        pz2[j] = pk2(sz[i], sz[i+1]);
        dist[2*j] = 1e10f; dist[2*j+1] = 1e10f;
    }
    float fx = sx[0], fy = sy[0], fz = sz[0];
    if (t == 0) g_fps[b*Sn] = 0;
    for (int it = 1; it < Sn; it++) {
        ull nx = pk2(-fx, -fx), ny = pk2(-fy, -fy), nz = pk2(-fz, -fz);
        float bv = -1.0f; int bi = 0;
#pragma unroll
        for (int j = 0; j < 4; j++) {
            ull dx = add2(px2[j], nx);
            ull dy = add2(py2[j], ny);
            ull dz = add2(pz2[j], nz);
            ull s  = add2(add2(mul2(dx,dx), mul2(dy,dy)), mul2(dz,dz));
            float dlo, dhi; upk2(s, dlo, dhi);
            float n0 = fminf(dist[2*j],   dlo); dist[2*j]   = n0;
            if (n0 > bv) { bv = n0; bi = t*8 + 2*j; }
            float n1 = fminf(dist[2*j+1], dhi); dist[2*j+1] = n1;
            if (n1 > bv) { bv = n1; bi = t*8 + 2*j + 1; }
        }
        unsigned dvb  = __float_as_uint(bv);
        unsigned wmax = __reduce_max_sync(0xffffffffu, dvb);
        unsigned cand = (dvb == wmax) ? (unsigned)bi : 0xffffffffu;
        unsigned wbi  = __reduce_min_sync(0xffffffffu, cand);
        int p = it & 1;
        if (lane == 0) { s_dv[p][warp] = wmax; s_di[p][warp] = wbi; }
        __syncthreads();
        unsigned v    = s_dv[p][lane];
        unsigned gmax = __reduce_max_sync(0xffffffffu, v);
        unsigned c2   = (v == gmax) ? s_di[p][lane] : 0xffffffffu;
        unsigned gbi  = __reduce_min_sync(0xffffffffu, c2);
        fx = sx[gbi]; fy = sy[gbi]; fz = sz[gbi];
        if (t == 0) g_fps[b*Sn + it] = (int)gbi;
    }
}

/* -------------------- new_xyz gather + small outputs --------------------- */
__global__ void k_newxyz(const float* __restrict__ xyz, float* __restrict__ out) {
    int i = blockIdx.x * blockDim.x + threadIdx.x;     /* center id 0..16383 */
    if (i >= Bn*Sn) return;
    int b = i / Sn, s = i % Sn;
    int n = g_fps[i];
    const float* xb = xyz + (size_t)b*3*Nn;
    float x = xb[n], y = xb[Nn+n], z = xb[2*Nn+n];
    g_newxyz[i*3+0]=x; g_newxyz[i*3+1]=y; g_newxyz[i*3+2]=z;
    out[((size_t)b*3+0)*Sn + s] = x;
    out[((size_t)b*3+1)*Sn + s] = y;
    out[((size_t)b*3+2)*Sn + s] = z;
    out[OXY2 + ((size_t)b*3+0)*Sn + s] = x;
    out[OXY2 + ((size_t)b*3+1)*Sn + s] = y;
    out[OXY2 + ((size_t)b*3+2)*Sn + s] = z;
    out[OFPS + i] = (float)n;
}

/* ------------------------------ ball query ------------------------------- */
#define BQC 2048
__global__ void __launch_bounds__(256) k_ballquery(const float* __restrict__ xyz) {
    __shared__ float sx[BQC], sy[BQC], sz[BQC];
    int blk = blockIdx.x;               /* 64 blocks: 8 per batch */
    int b = blk >> 3;
    int center = b*Sn + (blk & 7)*256 + threadIdx.x;
    int t = threadIdx.x;
    float cx = g_newxyz[center*3+0], cy = g_newxyz[center*3+1], cz = g_newxyz[center*3+2];
    const float* xb = xyz + (size_t)b*3*Nn;
    int found = 0, first = -1;
    for (int ch = 0; ch < Nn; ch += BQC) {
        for (int i = t; i < BQC; i += 256) {
            sx[i] = xb[ch+i]; sy[i] = xb[Nn+ch+i]; sz[i] = xb[2*Nn+ch+i];
        }
        __syncthreads();
        if (!__all_sync(0xffffffffu, found >= KS)) {
            for (int i = 0; i < BQC && found < KS; i++) {
                float dx = __fadd_rn(cx, -sx[i]);
                float dy = __fadd_rn(cy, -sy[i]);
                float dz = __fadd_rn(cz, -sz[i]);
                float d2 = __fadd_rn(__fadd_rn(__fmul_rn(dx,dx), __fmul_rn(dy,dy)),
                                     __fmul_rn(dz,dz));
                if (d2 <= R2c) {
                    if (first < 0) first = ch + i;
                    g_idx[center*KS + found] = ch + i;
                    found++;
                }
            }
        }
        if (__syncthreads_and(found >= KS)) break;
    }
    for (int i = found; i < KS; i++) g_idx[center*KS + i] = first;
}

/* -------------------- center-feature GEMV (layer-0 base) ----------------- */
__global__ void __launch_bounds__(256) k_base(const float* __restrict__ W0) {
    __shared__ float ws[67*64];
    __shared__ float cf[64*64];
    __shared__ float cxyz[64*3];
    int t = threadIdx.x;
    int c0 = blockIdx.x * 64;
    int b = c0 / Sn;
    for (int i = t; i < 67*64; i += 256) {
        int cc = i >> 6, o = i & 63;
        ws[i] = (cc < 3) ? W0[(size_t)o*131 + cc] : W0[(size_t)o*131 + 67 + (cc - 3)];
    }
    for (int i = t; i < 64*16; i += 256) {
        int row = i >> 4, seg = i & 15;
        int n = g_fps[c0 + row];
        float4 v = *(const float4*)&g_pts_t[((size_t)b*Nn + n)*Dn + seg*4];
        *(float4*)&cf[row*64 + seg*4] = v;
    }
    for (int i = t; i < 192; i += 256) cxyz[i] = g_newxyz[c0*3 + i];
    __syncthreads();
    int o4 = (t & 15) * 4, cg = t >> 4;
    float acc[4][4];
#pragma unroll
    for (int k = 0; k < 4; k++)
#pragma unroll
        for (int j = 0; j < 4; j++) acc[k][j] = 0.f;
#pragma unroll
    for (int cc = 0; cc < 3; cc++) {
        float4 wv = *(const float4*)&ws[cc*64 + o4];
#pragma unroll
        for (int k = 0; k < 4; k++) {
            float h = -cxyz[(cg*4 + k)*3 + cc];
            acc[k][0] += h*wv.x; acc[k][1] += h*wv.y;
            acc[k][2] += h*wv.z; acc[k][3] += h*wv.w;
        }
    }
#pragma unroll 8
    for (int cc = 3; cc < 67; cc++) {
        float4 wv = *(const float4*)&ws[cc*64 + o4];
#pragma unroll
        for (int k = 0; k < 4; k++) {
            float h = cf[(cg*4 + k)*64 + (cc - 3)];
            acc[k][0] += h*wv.x; acc[k][1] += h*wv.y;
            acc[k][2] += h*wv.z; acc[k][3] += h*wv.w;
        }
    }
#pragma unroll
    for (int k = 0; k < 4; k++) {
        float4 v = make_float4(acc[k][0], acc[k][1], acc[k][2], acc[k][3]);
        *(float4*)&g_base[(size_t)(c0 + cg*4 + k)*64 + o4] = v;
    }
}

#define FMA4(A, H, WV) { (A)[0] += (H)*(WV).x; (A)[1] += (H)*(WV).y; \
                         (A)[2] += (H)*(WV).z; (A)[3] += (H)*(WV).w; }

/* ------------------------------ layer 0 ---------------------------------- */
/* block: 4 tiles x (2 centers = 64 rows) x 64 outs; weights loaded once */
__global__ void __launch_bounds__(128) k_layer0(const float* __restrict__ xyz,
                                                const float* __restrict__ W0) {
    __shared__ float hs[64*72];
    __shared__ float ws[72*64];
    __shared__ int   idx_s[64];
    __shared__ float bs[128];
    __shared__ float ssum[64], ssq[64];
    int t = threadIdx.x;
    int b = (blockIdx.x * 8) / Sn;
    if (t < 64) { ssum[t] = 0.f; ssq[t] = 0.f; }
    for (int i = t; i < 72*64; i += 128) {
        int cc = i >> 6, o = i & 63;
        float v = 0.f;
        if (cc < 64)      v = W0[(size_t)o*131 + 3 + cc];
        else if (cc < 67) v = W0[(size_t)o*131 + (cc - 64)];
        ws[cc*64 + o] = v;
    }
    const float* xb = xyz + (size_t)b*3*Nn;
    int rg = t >> 4, og = t & 15;
    float tps[4] = {0,0,0,0}, tpq[4] = {0,0,0,0};
    for (int tile = 0; tile < 4; tile++) {
        int c0 = blockIdx.x * 8 + tile * 2;
        __syncthreads();
        if (t < 64) idx_s[t] = g_idx[c0*KS + t];
        bs[t] = g_base[(size_t)c0*64 + t];
        __syncthreads();
        for (int i = t; i < 64*16; i += 128) {
            int row = i >> 4, seg = i & 15;
            int n = idx_s[row];
            float4 v = *(const float4*)&g_pts_t[((size_t)b*Nn + n)*Dn + seg*4];
            *(float4*)&hs[row*72 + seg*4] = v;
        }
        for (int i = t; i < 64*8; i += 128) {
            int row = i >> 3, cc = i & 7;
            int n = idx_s[row];
            float v = 0.f;
            if (cc < 3) v = xb[cc*Nn + n];
            hs[row*72 + 64 + cc] = v;
        }
        __syncthreads();
        float acc[32];
#pragma unroll
        for (int i = 0; i < 32; i++) acc[i] = 0.f;
#pragma unroll
        for (int cs = 0; cs < 72; cs += 4) {
            float4 wv[4];
#pragma unroll
            for (int i = 0; i < 4; i++) wv[i] = *(const float4*)&ws[(cs+i)*64 + og*4];
#pragma unroll
            for (int j = 0; j < 8; j++) {
                float4 hv = *(const float4*)&hs[(rg*8+j)*72 + cs];
                FMA4(&acc[j*4], hv.x, wv[0]);
                FMA4(&acc[j*4], hv.y, wv[1]);
                FMA4(&acc[j*4], hv.z, wv[2]);
                FMA4(&acc[j*4], hv.w, wv[3]);
            }
        }
#pragma unroll
        for (int j = 0; j < 8; j++) {
            int row = rg*8 + j;
            int cl = row >> 5;
            float4 zv;
            zv.x = acc[j*4+0] + bs[cl*64 + og*4+0];
            zv.y = acc[j*4+1] + bs[cl*64 + og*4+1];
            zv.z = acc[j*4+2] + bs[cl*64 + og*4+2];
            zv.w = acc[j*4+3] + bs[cl*64 + og*4+3];
            *(float4*)&g_h0[((size_t)c0*KS + row)*64 + og*4] = zv;
            tps[0]+=zv.x; tps[1]+=zv.y; tps[2]+=zv.z; tps[3]+=zv.w;
            tpq[0]+=zv.x*zv.x; tpq[1]+=zv.y*zv.y; tpq[2]+=zv.z*zv.z; tpq[3]+=zv.w*zv.w;
        }
    }
#pragma unroll
    for (int i = 0; i < 4; i++) {
        atomicAdd(&ssum[og*4+i], tps[i]);
        atomicAdd(&ssq[og*4+i],  tpq[i]);
    }
    __syncthreads();
    if (t < 64) {
        atomicAdd(&g_sum[0][t], (double)ssum[t]);
        atomicAdd(&g_sq[0][t],  (double)ssq[t]);
    }
}

/* ------------------------------ layer 1 ---------------------------------- */
/* 8x8 register tile: block = 2 tiles x 128 rows x 64 outs, 128 threads */
__global__ void __launch_bounds__(128) k_layer1(const float* __restrict__ W1) {
    __shared__ float hs[128*64];
    __shared__ float ws[64*64];
    __shared__ float ssum[64], ssq[64];
    int t = threadIdx.x;
    if (t < 64) { ssum[t] = 0.f; ssq[t] = 0.f; }
    for (int i = t; i < 64*64; i += 128) {
        int cc = i >> 6, o = i & 63;
        ws[cc*64 + o] = W1[(size_t)o*64 + cc];
    }
    int rg = t >> 3, og = (t & 7) * 8;
    for (int tile = 0; tile < 2; tile++) {
        size_t m0 = (size_t)blockIdx.x * 256 + tile * 128;
        __syncthreads();
        for (int i = t; i < 128*16; i += 128) {
            int row = i >> 4, seg = i & 15;
            float4 v = *(const float4*)&g_h0[(m0 + row)*64 + seg*4];
            v.x = fmaxf(g_sc[0][seg*4+0]*v.x + g_sh[0][seg*4+0], 0.f);
            v.y = fmaxf(g_sc[0][seg*4+1]*v.y + g_sh[0][seg*4+1], 0.f);
            v.z = fmaxf(g_sc[0][seg*4+2]*v.z + g_sh[0][seg*4+2], 0.f);
            v.w = fmaxf(g_sc[0][seg*4+3]*v.w + g_sh[0][seg*4+3], 0.f);
            *(float4*)&hs[row*64 + seg*4] = v;
        }
        __syncthreads();
        float acc[64];
#pragma unroll
        for (int i = 0; i < 64; i++) acc[i] = 0.f;
#pragma unroll
        for (int cs = 0; cs < 64; cs += 4) {
            float4 wv[8];
#pragma unroll
            for (int c = 0; c < 4; c++) {
                wv[c*2]   = *(const float4*)&ws[(cs+c)*64 + og];
                wv[c*2+1] = *(const float4*)&ws[(cs+c)*64 + og + 4];
            }
#pragma unroll
            for (int j = 0; j < 8; j++) {
                float4 hv = *(const float4*)&hs[(rg*8+j)*64 + cs];
                float* a = &acc[j*8];
                FMA4(a,   hv.x, wv[0]); FMA4(a+4, hv.x, wv[1]);
                FMA4(a,   hv.y, wv[2]); FMA4(a+4, hv.y, wv[3]);
                FMA4(a,   hv.z, wv[4]); FMA4(a+4, hv.z, wv[5]);
                FMA4(a,   hv.w, wv[6]); FMA4(a+4, hv.w, wv[7]);
            }
        }
        float ps[8] = {0,0,0,0,0,0,0,0}, pq[8] = {0,0,0,0,0,0,0,0};
#pragma unroll
        for (int j = 0; j < 8; j++) {
            int row = rg*8 + j;
            float4 z0 = make_float4(acc[j*8+0], acc[j*8+1], acc[j*8+2], acc[j*8+3]);
            float4 z1 = make_float4(acc[j*8+4], acc[j*8+5], acc[j*8+6], acc[j*8+7]);
            *(float4*)&g_h1[(m0 + row)*64 + og]     = z0;
            *(float4*)&g_h1[(m0 + row)*64 + og + 4] = z1;
#pragma unroll
            for (int k = 0; k < 8; k++) {
                float z = acc[j*8+k];
                ps[k] += z; pq[k] += z*z;
            }
        }
#pragma unroll
        for (int k = 0; k < 8; k++) {
            atomicAdd(&ssum[og+k], ps[k]);
            atomicAdd(&ssq[og+k],  pq[k]);
        }
    }
    __syncthreads();
    if (t < 64) {
        atomicAdd(&g_sum[1][t], (double)ssum[t]);
        atomicAdd(&g_sq[1][t],  (double)ssq[t]);
    }
}

/* ------------------------------ layer 2 ---------------------------------- */
/* 8x8 register tile: block = 2 tiles x (2 centers = 64 rows) x 128 outs,
   128 threads; h2 never materialized (max+min carried) */
__global__ void __launch_bounds__(128) k_layer2(const float* __restrict__ W2) {
    extern __shared__ float dyn[];
    float* hs    = dyn;                  /* 64*64  = 4096  */
    float* ws    = dyn + 4096;           /* 64*128 = 8192  */
    float* redmx = dyn + 4096 + 8192;    /* 8*128  = 1024  */
    float* redmn = redmx + 1024;         /* 1024  */
    float* ssum  = redmn + 1024;         /* 128   */
    float* ssq   = ssum + 128;           /* 128   */
    int t = threadIdx.x;
    if (t < 128) { ssum[t] = 0.f; ssq[t] = 0.f; }
    for (int i = t; i < 64*128; i += 128) {
        int cc = i >> 7, o = i & 127;
        ws[cc*128 + o] = W2[(size_t)o*64 + cc];
    }
    int rg = t >> 4, og = (t & 15) * 8;
    for (int tile = 0; tile < 2; tile++) {
        int c0 = blockIdx.x * 4 + tile * 2;
        size_t m0 = (size_t)c0 * KS;
        __syncthreads();
        for (int i = t; i < 64*16; i += 128) {
            int row = i >> 4, seg = i & 15;
            float4 v = *(const float4*)&g_h1[(m0 + row)*64 + seg*4];
            v.x = fmaxf(g_sc[1][seg*4+0]*v.x + g_sh[1][seg*4+0], 0.f);
            v.y = fmaxf(g_sc[1][seg*4+1]*v.y + g_sh[1][seg*4+1], 0.f);
            v.z = fmaxf(g_sc[1][seg*4+2]*v.z + g_sh[1][seg*4+2], 0.f);
            v.w = fmaxf(g_sc[1][seg*4+3]*v.w + g_sh[1][seg*4+3], 0.f);
            *(float4*)&hs[row*64 + seg*4] = v;
        }
        __syncthreads();
        float acc[64];
#pragma unroll
        for (int i = 0; i < 64; i++) acc[i] = 0.f;
#pragma unroll
        for (int cs = 0; cs < 64; cs += 4) {
            float4 wv[8];
#pragma unroll
            for (int c = 0; c < 4; c++) {
                wv[c*2]   = *(const float4*)&ws[(cs+c)*128 + og];
                wv[c*2+1] = *(const float4*)&ws[(cs+c)*128 + og + 4];
            }
#pragma unroll
            for (int j = 0; j < 8; j++) {
                float4 hv = *(const float4*)&hs[(rg*8+j)*64 + cs];
                float* a = &acc[j*8];
                FMA4(a,   hv.x, wv[0]); FMA4(a+4, hv.x, wv[1]);
                FMA4(a,   hv.y, wv[2]); FMA4(a+4, hv.y, wv[3]);
                FMA4(a,   hv.z, wv[4]); FMA4(a+4, hv.z, wv[5]);
                FMA4(a,   hv.w, wv[6]); FMA4(a+4, hv.w, wv[7]);
            }
        }
        /* epilogue: this thread's 8 rows are all in center c0 + (rg>>2) */
#pragma unroll
        for (int k = 0; k < 8; k++) {
            int o = og + k;
            float mx = -1e30f, mn = 1e30f, ps = 0.f, pq = 0.f;
#pragma unroll
            for (int j = 0; j < 8; j++) {
                float z = acc[j*8+k];
                mx = fmaxf(mx, z); mn = fminf(mn, z);
                ps += z; pq += z*z;
            }
            redmx[rg*128 + o] = mx;
            redmn[rg*128 + o] = mn;
            atomicAdd(&ssum[o], ps);
            atomicAdd(&ssq[o],  pq);
        }
        __syncthreads();
#pragma unroll
        for (int p = t; p < 256; p += 128) {
            int cl = p >> 7, o = p & 127;
            float mx = -1e30f, mn = 1e30f;
#pragma unroll
            for (int r = 0; r < 4; r++) {
                mx = fmaxf(mx, redmx[(cl*4+r)*128 + o]);
                mn = fminf(mn, redmn[(cl*4+r)*128 + o]);
            }
            g_mx[(size_t)(c0+cl)*128 + o] = mx;
            g_mn[(size_t)(c0+cl)*128 + o] = mn;
        }
    }
    __syncthreads();
    if (t < 128) {
        atomicAdd(&g_sum[2][t], (double)ssum[t]);
        atomicAdd(&g_sq[2][t],  (double)ssq[t]);
    }
}

/* ----------------------------- BN fold ----------------------------------- */
__global__ void k_stats(int layer, const float* __restrict__ gm,
                        const float* __restrict__ bt, int nch) {
    int c = threadIdx.x;
    if (c < nch) {
        double mu = g_sum[layer][c] / (double)MTOT;
        double vr = g_sq[layer][c] / (double)MTOT - mu*mu;
        float sc = gm[c] * rsqrtf((float)vr + 1e-5f);
        g_sc[layer][c] = sc;
        g_sh[layer][c] = bt[c] - (float)mu * sc;
    }
}

/* ----------------------------- final pool -------------------------------- */
__global__ void k_final(float* __restrict__ out) {
    int i = blockIdx.x * blockDim.x + threadIdx.x;
    if (i >= Bn*Sn*128) return;
    int center = i >> 7, o = i & 127;
    int b = center / Sn, s = center % Sn;
    float sc = g_sc[2][o], sh = g_sh[2][o];
    float z = (sc >= 0.f) ? g_mx[(size_t)center*128 + o] : g_mn[(size_t)center*128 + o];
    out[ONP + ((size_t)b*128 + o)*Sn + s] = fmaxf(sc*z + sh, 0.f);
}

/* ------------------------------- launch ---------------------------------- */
extern "C" void kernel_launch(void* const* d_in, const int* in_sizes, int n_in,
                              void* d_out, int out_size) {
    const float* xyz = (const float*)d_in[0];
    const float* pts = (const float*)d_in[1];
    const float* W0  = (const float*)d_in[2];
    const float* g0  = (const float*)d_in[3];
    const float* b0  = (const float*)d_in[4];
    const float* W1  = (const float*)d_in[5];
    const float* g1  = (const float*)d_in[6];
    const float* b1  = (const float*)d_in[7];
    const float* W2  = (const float*)d_in[8];
    const float* g2  = (const float*)d_in[9];
    const float* b2  = (const float*)d_in[10];
    float* out = (float*)d_out;

    static bool attr_done = false;
    if (!attr_done) {
        cudaFuncSetAttribute(k_fps, cudaFuncAttributeMaxDynamicSharedMemorySize,
                             3*Nn*sizeof(float));
        cudaFuncSetAttribute(k_layer2, cudaFuncAttributeMaxDynamicSharedMemorySize,
                             (4096+8192+1024+1024+256)*sizeof(float));
        attr_done = true;
    }

    k_zero<<<1, 128>>>();
    k_transpose<<<dim3(Nn/32, Dn/32, Bn), dim3(32, 8)>>>(pts);
    k_dummy<<<1, 32>>>();                               /* ncu alignment: fps = #6 */
    k_fps<<<Bn, 1024, 3*Nn*sizeof(float)>>>(xyz);
    k_newxyz<<<(Bn*Sn + 255)/256, 256>>>(xyz, out);
    k_ballquery<<<64, 256>>>(xyz);
    k_base<<<256, 256>>>(W0);
    k_layer0<<<Bn*Sn/8, 128>>>(xyz, W0);
    k_stats<<<1, 128>>>(0, g0, b0, 64);
    k_layer1<<<MTOT/256, 128>>>(W1);
    k_stats<<<1, 128>>>(1, g1, b1, 64);
    k_layer2<<<Bn*Sn/4, 128, (4096+8192+1024+1024+256)*sizeof(float)>>>(W2);
    k_stats<<<1, 128>>>(2, g2, b2, 128);
    k_final<<<(Bn*Sn*128 + 255)/256, 256>>>(out);
}